// round 16
// baseline (speedup 1.0000x reference)
#include <cuda_runtime.h>
#include <cuda_fp16.h>
#include <mma.h>
#include <cstdint>
#include <cstddef>

using namespace nvcuda;

#define S_DIM 2048
#define DIN 4096
#define DOUT 11008
#define REMAINED 3852

#define T_FLAG 1.5e-6f
#define NZ_TVMAX 4e-6f
#define BAND 3
#define LIST_CAP 131072

// Output layout (float32 concat): tv | filtered_W | filtered_bias | indices
#define OFF_TV   ((size_t)0)
#define N_TV     ((size_t)S_DIM * DOUT)
#define OFF_W    (N_TV)
#define N_W      ((size_t)REMAINED * DIN)
#define OFF_BIAS (OFF_W + N_W)
#define OFF_IDX  (OFF_BIAS + REMAINED)

// Scratch (device globals — no allocation allowed)
__device__ int g_counts[DOUT];
__device__ int g_pos;
__device__ int g_limit;
__device__ int g_indices[REMAINED];
__device__ float g_sfast[(size_t)S_DIM * DOUT];
__device__ __half g_xh[(size_t)S_DIM * DIN];
__device__ __half g_wh[(size_t)DOUT * DIN];
__device__ unsigned short g_key[(size_t)S_DIM * DOUT];
__device__ int  g_nz_cnt;
__device__ int2 g_nz[LIST_CAP];
__device__ int  g_bd_cnt;
__device__ int2 g_bd[LIST_CAP];

// ---------------------------------------------------------------------------
__global__ void init_kernel() {
    int i = blockIdx.x * blockDim.x + threadIdx.x;
    if (i < DOUT) g_counts[i] = 0;
    if (i == 0) { g_pos = 0; g_nz_cnt = 0; g_bd_cnt = 0; }
}

// ---------------------------------------------------------------------------
// Exact f32 -> f16 pre-conversion (values are f16 images). 8 elems/thread.
// ---------------------------------------------------------------------------
__global__ void convert_kernel(const float* __restrict__ src,
                               __half* __restrict__ dst, int n8) {
    int i = blockIdx.x * blockDim.x + threadIdx.x;
    if (i >= n8) return;
    float4 v0 = *((const float4*)src + i * 2);
    float4 v1 = *((const float4*)src + i * 2 + 1);
    uint4 p;
    ((__half2*)&p)[0] = __floats2half2_rn(v0.x, v0.y);
    ((__half2*)&p)[1] = __floats2half2_rn(v0.z, v0.w);
    ((__half2*)&p)[2] = __floats2half2_rn(v1.x, v1.y);
    ((__half2*)&p)[3] = __floats2half2_rn(v1.z, v1.w);
    *((uint4*)dst + i) = p;
}

// ---------------------------------------------------------------------------
// Flag / key helpers (validated rounds 9-15)
// ---------------------------------------------------------------------------
__device__ __forceinline__ unsigned short hnext(unsigned short b) {
    if (b == 0x8000u) return 0x0001u;
    return (b & 0x8000u) ? (unsigned short)(b - 1) : (unsigned short)(b + 1);
}
__device__ __forceinline__ unsigned short hprev(unsigned short b) {
    if (b == 0x0000u) return 0x8001u;
    return (b & 0x8000u) ? (unsigned short)(b + 1) : (unsigned short)(b - 1);
}
__device__ __forceinline__ bool unsafe_val(float s) {
    __half h = __float2half_rn(s);
    unsigned short b = __half_as_ushort(h);
    float hv = __half2float(h);
    float up = __half2float(__ushort_as_half(hnext(b)));
    float dn = __half2float(__ushort_as_half(hprev(b)));
    return (0.5f * (hv + up) - s < T_FLAG) || (s - 0.5f * (hv + dn) < T_FLAG);
}
__device__ __forceinline__ unsigned key16f(float f) {
    unsigned short b = __half_as_ushort(__float2half(f));
    if (b == 0x8000u) b = 0;
    return (b & 0x8000u) ? (unsigned)(0xFFFFu ^ b) : (unsigned)(b | 0x8000u);
}

// ---------------------------------------------------------------------------
// FAST GEMM + fused epilogue: f16 wmma, f32 acc, cp.async 3-stage, 128x256,
// GBK=64. Per-element chunk order ascending (bit-identical g_sfast).
// ---------------------------------------------------------------------------
#define GBM 128
#define GBN 256
#define GBK 64
#define PAD 72
#define NSTAGE 3
#define STAGE_HALVES ((GBM + GBN) * PAD)

__device__ __forceinline__ void cp16(void* dst, const void* src) {
    unsigned ds = (unsigned)__cvta_generic_to_shared(dst);
    asm volatile("cp.async.cg.shared.global [%0], [%1], 16;"
                 :: "r"(ds), "l"(src));
}

__global__ void __launch_bounds__(256) gemm_fast_kernel(
        const float* __restrict__ bias, float* __restrict__ out,
        float* __restrict__ gs) {
    extern __shared__ char smem[];
    __half* stg = (__half*)smem;     // NSTAGE stages: [A 128*PAD | B 256*PAD]
    float* Cs = (float*)smem;        // reused after mainloop: [128][256]

    int tid  = threadIdx.x;
    int warp = tid >> 5;
    int wm   = warp >> 2;
    int wn   = warp & 3;
    int rowBase = blockIdx.y * GBM;
    int colBase = blockIdx.x * GBN;

    wmma::fragment<wmma::accumulator, 16, 16, 16, float> acc[4][4];
#pragma unroll
    for (int i = 0; i < 4; i++)
#pragma unroll
        for (int j = 0; j < 4; j++) wmma::fill_fragment(acc[i][j], 0.0f);

    auto loadStage = [&](int st, int k0) {
        __half* As = stg + st * STAGE_HALVES;
        __half* Bs = As + GBM * PAD;
        const __half* xa = g_xh + (size_t)rowBase * DIN + k0;
        const __half* wb = g_wh + (size_t)colBase * DIN + k0;
#pragma unroll
        for (int p = 0; p < 4; p++) {
            int idx = tid + p * 256;
            int r = idx >> 3, q = idx & 7;
            cp16(&As[r * PAD + q * 8], xa + (size_t)r * DIN + q * 8);
        }
#pragma unroll
        for (int p = 0; p < 8; p++) {
            int idx = tid + p * 256;
            int r = idx >> 3, q = idx & 7;
            cp16(&Bs[r * PAD + q * 8], wb + (size_t)r * DIN + q * 8);
        }
        asm volatile("cp.async.commit_group;");
    };

    loadStage(0, 0);
    loadStage(1, GBK);

    const int NSTEP = DIN / GBK;   // 64
    for (int c = 0; c < NSTEP; c++) {
        asm volatile("cp.async.wait_group 1;");
        __syncthreads();
        if (c + 2 < NSTEP) loadStage((c + 2) % NSTAGE, (c + 2) * GBK);
        const __half* Ab = stg + (c % NSTAGE) * STAGE_HALVES;
        const __half* Bb = Ab + GBM * PAD;
#pragma unroll
        for (int kk = 0; kk < GBK; kk += 16) {
            wmma::fragment<wmma::matrix_a, 16, 16, 16, __half, wmma::row_major> af[4];
            wmma::fragment<wmma::matrix_b, 16, 16, 16, __half, wmma::col_major> bf[4];
#pragma unroll
            for (int i = 0; i < 4; i++)
                wmma::load_matrix_sync(af[i], Ab + (wm * 64 + i * 16) * PAD + kk, PAD);
#pragma unroll
            for (int j = 0; j < 4; j++)
                wmma::load_matrix_sync(bf[j], Bb + (wn * 64 + j * 16) * PAD + kk, PAD);
#pragma unroll
            for (int i = 0; i < 4; i++)
#pragma unroll
                for (int j = 0; j < 4; j++)
                    wmma::mma_sync(acc[i][j], af[i], bf[j], acc[i][j]);
        }
    }

    // drain async, then stage C through smem (reuses stage memory)
    asm volatile("cp.async.wait_group 0;");
    __syncthreads();
#pragma unroll
    for (int i = 0; i < 4; i++)
#pragma unroll
        for (int j = 0; j < 4; j++)
            wmma::store_matrix_sync(Cs + (wm * 64 + i * 16) * GBN + wn * 64 + j * 16,
                                    acc[i][j], GBN, wmma::mem_row_major);
    __syncthreads();

    // fused epilogue: 8192 float4 over the 128x256 tile
    int pos = 0;
#pragma unroll 4
    for (int e = 0; e < 32; e++) {
        int lin4 = tid + 256 * e;
        int r = lin4 >> 6, c4 = lin4 & 63;
        int row = rowBase + r;
        int col0 = colBase + c4 * 4;
        float4 s = *((float4*)(Cs + r * GBN) + c4);
        float4 b = *((const float4*)(bias + col0));
        float sv[4] = {s.x, s.y, s.z, s.w};
        float bv[4] = {b.x, b.y, b.z, b.w};
        float tv[4];
        ushort4 kv;
        unsigned short* kp = (unsigned short*)&kv;
#pragma unroll
        for (int q = 0; q < 4; q++) {
            __half hmm = __float2half(sv[q]);
            float tvf = __half2float(hmm) + bv[q];
            __half h = __float2half(tvf);
            tv[q] = __half2float(h);
            kp[q] = (unsigned short)key16f(tv[q]);
            pos += (tv[q] > 0.0f) ? 1 : 0;
            if (fabsf(tv[q]) < NZ_TVMAX) {
                int idx = atomicAdd(&g_nz_cnt, 1);
                if (idx < LIST_CAP) g_nz[idx] = make_int2(row, col0 + q);
            }
        }
        size_t o = (size_t)row * DOUT + col0;
        *((float4*)(gs + o)) = s;
        *((float4*)(out + OFF_TV + o)) = make_float4(tv[0], tv[1], tv[2], tv[3]);
        *((ushort4*)(g_key + o)) = kv;
    }
#pragma unroll
    for (int off = 16; off; off >>= 1) pos += __shfl_down_sync(~0u, pos, off);
    __shared__ int spos[8];
    if ((tid & 31) == 0) spos[warp] = pos;
    __syncthreads();
    if (tid == 0) {
        int t = 0;
        for (int k = 0; k < 8; k++) t += spos[k];
        if (t) atomicAdd(&g_pos, t);
    }
}

// ---------------------------------------------------------------------------
// Exact-chain recompute (round-7-bit-identical): ascending k, kc=320 panels.
// ---------------------------------------------------------------------------
__global__ void recompute_list_kernel(const float* __restrict__ bias,
                                      float* __restrict__ out, int which) {
    int cnt = (which == 0) ? g_nz_cnt : g_bd_cnt;
    if (cnt > LIST_CAP) cnt = LIST_CAP;
    const int2* list = (which == 0) ? g_nz : g_bd;
    int posDelta = 0;

    for (int idx = blockIdx.x * blockDim.x + threadIdx.x; idx < cnt;
         idx += gridDim.x * blockDim.x) {
        int row = list[idx].x, col = list[idx].y;
        const __half* xp = g_xh + (size_t)row * DIN;
        const __half* wp = g_wh + (size_t)col * DIN;
        float accT = 0.0f;
        int k = 0;
#pragma unroll 1
        for (int t = 0; t < 13; t++) {
            int kend = (t < 12) ? (t + 1) * 320 : DIN;
            float accC = 0.0f;
#pragma unroll 1
            for (; k < kend; k += 16) {
                uint4 xa = *(const uint4*)(xp + k);
                uint4 wa = *(const uint4*)(wp + k);
                uint4 xb = *(const uint4*)(xp + k + 8);
                uint4 wb = *(const uint4*)(wp + k + 8);
#pragma unroll
                for (int q = 0; q < 4; q++) {
                    float2 xf = __half22float2(((const __half2*)&xa)[q]);
                    float2 wf = __half22float2(((const __half2*)&wa)[q]);
                    accC = __fmaf_rn(xf.x, wf.x, accC);
                    accC = __fmaf_rn(xf.y, wf.y, accC);
                }
#pragma unroll
                for (int q = 0; q < 4; q++) {
                    float2 xf = __half22float2(((const __half2*)&xb)[q]);
                    float2 wf = __half22float2(((const __half2*)&wb)[q]);
                    accC = __fmaf_rn(xf.x, wf.x, accC);
                    accC = __fmaf_rn(xf.y, wf.y, accC);
                }
            }
            accT = accT + accC;
        }
        __half hmm = __float2half(accT);
        float tvf = __half2float(hmm) + bias[col];
        __half h = __float2half(tvf);
        float hv = __half2float(h);
        size_t o = (size_t)row * DOUT + col;
        float old = out[OFF_TV + o];
        if (which == 0)
            posDelta += ((hv > 0.0f) ? 1 : 0) - ((old > 0.0f) ? 1 : 0);
        out[OFF_TV + o] = hv;
        g_key[o] = (unsigned short)key16f(hv);
    }
    if (which == 0) {
#pragma unroll
        for (int off = 16; off; off >>= 1)
            posDelta += __shfl_down_sync(~0u, posDelta, off);
        if ((threadIdx.x & 31) == 0 && posDelta != 0) atomicAdd(&g_pos, posDelta);
    }
}

// ---------------------------------------------------------------------------
__global__ void limit_kernel() {
    g_limit = (int)floorf((0.2f * (float)g_pos) / 2048.0f);
}

// ---------------------------------------------------------------------------
// Phase A: per row (keys only), fast threshold K; collect flagged band elems.
// ---------------------------------------------------------------------------
__global__ void topmask_find_kernel() {
    int row = blockIdx.x;
    int limit = g_limit;
    if (limit <= 0) return;

    __shared__ int hist[256];
    __shared__ int sB, sChi, sK;
    int tid = threadIdx.x;
    const unsigned short* kr = g_key + (size_t)row * DOUT;

    hist[tid] = 0;
    __syncthreads();
    for (int j = tid; j < DOUT; j += 256)
        atomicAdd(&hist[kr[j] >> 8], 1);
    __syncthreads();
    if (tid == 0) {
        int c = 0, b = 255;
        for (; b > 0; b--) {
            if (c + hist[b] >= limit) break;
            c += hist[b];
        }
        sB = b; sChi = c;
    }
    __syncthreads();
    int b = sB, chi = sChi;

    hist[tid] = 0;
    __syncthreads();
    for (int j = tid; j < DOUT; j += 256) {
        unsigned u = kr[j];
        if ((int)(u >> 8) == b) atomicAdd(&hist[u & 255], 1);
    }
    __syncthreads();
    if (tid == 0) {
        int c = chi, lb = 255;
        for (; lb > 0; lb--) {
            if (c + hist[lb] >= limit) break;
            c += hist[lb];
        }
        sK = (b << 8) | lb;
    }
    __syncthreads();
    int K = sK;

    for (int j = tid; j < DOUT; j += 256) {
        int key = (int)kr[j];
        if (key >= K - BAND && key <= K + BAND) {
            float s = g_sfast[(size_t)row * DOUT + j];
            if (unsafe_val(s)) {
                int idx = atomicAdd(&g_bd_cnt, 1);
                if (idx < LIST_CAP) g_bd[idx] = make_int2(row, j);
            }
        }
    }
}

// ---------------------------------------------------------------------------
// Phase B: exact per-row top-limit selection on corrected keys.
// ---------------------------------------------------------------------------
__global__ void topmask_kernel() {
    int row = blockIdx.x;
    int limit = g_limit;
    if (limit <= 0) return;

    __shared__ int hist[256];
    __shared__ int scan[256];
    __shared__ int sB, sChi, sK, sNeed;
    int tid = threadIdx.x;
    const unsigned short* kr = g_key + (size_t)row * DOUT;

    hist[tid] = 0;
    __syncthreads();
    for (int j = tid; j < DOUT; j += 256)
        atomicAdd(&hist[kr[j] >> 8], 1);
    __syncthreads();
    if (tid == 0) {
        int c = 0, b = 255;
        for (; b > 0; b--) {
            if (c + hist[b] >= limit) break;
            c += hist[b];
        }
        sB = b; sChi = c;
    }
    __syncthreads();
    int b = sB, chi = sChi;

    hist[tid] = 0;
    __syncthreads();
    for (int j = tid; j < DOUT; j += 256) {
        unsigned u = kr[j];
        if ((int)(u >> 8) == b) atomicAdd(&hist[u & 255], 1);
    }
    __syncthreads();
    if (tid == 0) {
        int c = chi, lb = 255;
        for (; lb > 0; lb--) {
            if (c + hist[lb] >= limit) break;
            c += hist[lb];
        }
        sK = (b << 8) | lb;
        sNeed = limit - c;
    }
    __syncthreads();
    unsigned K = (unsigned)sK;
    int need = sNeed;

    int j0 = tid * 43;
    int myTies = 0;
    for (int j = j0; j < j0 + 43; j++) {
        unsigned u = kr[j];
        if (u > K) atomicAdd(&g_counts[j], 1);
        else if (u == K) myTies++;
    }
    scan[tid] = myTies;
    __syncthreads();
    for (int off = 1; off < 256; off <<= 1) {
        int t = (tid >= off) ? scan[tid - off] : 0;
        __syncthreads();
        scan[tid] += t;
        __syncthreads();
    }
    int rank = scan[tid] - myTies;
    if (myTies > 0) {
        for (int j = j0; j < j0 + 43; j++) {
            if (kr[j] == K) {
                if (rank < need) atomicAdd(&g_counts[j], 1);
                rank++;
            }
        }
    }
}

// ---------------------------------------------------------------------------
__global__ void sort_kernel(const float* __restrict__ bias, float* __restrict__ out) {
    extern __shared__ unsigned keys[];
    int tid = threadIdx.x;
    for (int i = tid; i < 16384; i += 1024) {
        int cnt = (i < DOUT) ? g_counts[i] : 0;
        keys[i] = ((unsigned)cnt << 14) | (unsigned)(16383 - i);
    }
    __syncthreads();
    for (unsigned k = 2; k <= 16384; k <<= 1) {
        for (unsigned j = k >> 1; j > 0; j >>= 1) {
            for (int i = tid; i < 16384; i += 1024) {
                unsigned ixj = (unsigned)i ^ j;
                if (ixj > (unsigned)i) {
                    unsigned a = keys[i], c = keys[ixj];
                    bool desc = ((i & k) == 0);
                    if (desc ? (a < c) : (a > c)) { keys[i] = c; keys[ixj] = a; }
                }
            }
            __syncthreads();
        }
    }
    for (int i = tid; i < REMAINED; i += 1024) {
        int idx = 16383 - (int)(keys[i] & 16383u);
        g_indices[i] = idx;
        out[OFF_BIAS + i] = bias[idx];
        out[OFF_IDX + i]  = (float)idx;
    }
}

// ---------------------------------------------------------------------------
__global__ void gather_kernel(const float* __restrict__ w, float* __restrict__ out) {
    int i = blockIdx.x * blockDim.x + threadIdx.x;
    const int total8 = REMAINED * (DIN / 8);
    if (i >= total8) return;
    int r = i / (DIN / 8);
    int c8 = i % (DIN / 8);
    int src = g_indices[r];
    const float* s = w + (size_t)src * DIN + (size_t)c8 * 8;
    float* o = out + OFF_W + (size_t)r * DIN + (size_t)c8 * 8;
    float4 v0 = *(const float4*)(s);
    float4 v1 = *(const float4*)(s + 4);
    *(float4*)(o)     = v0;
    *(float4*)(o + 4) = v1;
}

// ---------------------------------------------------------------------------
extern "C" void kernel_launch(void* const* d_in, const int* in_sizes, int n_in,
                              void* d_out, int out_size) {
    const float* x    = (const float*)d_in[0];
    const float* w    = (const float*)d_in[1];
    const float* bias = (const float*)d_in[2];
    float* out = (float*)d_out;

    static __half* xh_p = nullptr;
    static __half* wh_p = nullptr;
    static float* sfast_p = nullptr;
    if (!xh_p) {
        cudaGetSymbolAddress((void**)&xh_p, g_xh);
        cudaGetSymbolAddress((void**)&wh_p, g_wh);
        cudaGetSymbolAddress((void**)&sfast_p, g_sfast);
    }

    int gemm_smem = NSTAGE * STAGE_HALVES * 2;            // 165888
    if (gemm_smem < GBM * GBN * 4) gemm_smem = GBM * GBN * 4;
    cudaFuncSetAttribute(gemm_fast_kernel, cudaFuncAttributeMaxDynamicSharedMemorySize, gemm_smem);
    cudaFuncSetAttribute(sort_kernel, cudaFuncAttributeMaxDynamicSharedMemorySize, 65536);

    init_kernel<<<(DOUT + 255) / 256, 256>>>();
    convert_kernel<<<(S_DIM * DIN / 8 + 255) / 256, 256>>>(x, xh_p, S_DIM * DIN / 8);
    convert_kernel<<<(DOUT * DIN / 8 + 255) / 256, 256>>>(w, wh_p, DOUT * DIN / 8);
    gemm_fast_kernel<<<dim3(DOUT / GBN, S_DIM / GBM), 256, gemm_smem>>>(bias, out, sfast_p);
    recompute_list_kernel<<<64, 256>>>(bias, out, 0);
    limit_kernel<<<1, 1>>>();
    topmask_find_kernel<<<S_DIM, 256>>>();
    recompute_list_kernel<<<64, 256>>>(bias, out, 1);
    topmask_kernel<<<S_DIM, 256>>>();
    sort_kernel<<<1, 1024, 65536>>>(bias, out);
    gather_kernel<<<(REMAINED * (DIN / 8) + 255) / 256, 256>>>(w, out);
}

// round 17
// speedup vs baseline: 1.5664x; 1.5664x over previous
#include <cuda_runtime.h>
#include <cuda_fp16.h>
#include <mma.h>
#include <cstdint>
#include <cstddef>

using namespace nvcuda;

#define S_DIM 2048
#define DIN 4096
#define DOUT 11008
#define REMAINED 3852

#define T_FLAG 1.5e-6f
#define NZ_TVMAX 4e-6f
#define BAND 3
#define LIST_CAP 131072

// Output layout (float32 concat): tv | filtered_W | filtered_bias | indices
#define OFF_TV   ((size_t)0)
#define N_TV     ((size_t)S_DIM * DOUT)
#define OFF_W    (N_TV)
#define N_W      ((size_t)REMAINED * DIN)
#define OFF_BIAS (OFF_W + N_W)
#define OFF_IDX  (OFF_BIAS + REMAINED)

// Scratch (device globals — no allocation allowed)
__device__ int g_counts[DOUT];
__device__ int g_pos;
__device__ int g_limit;
__device__ int g_indices[REMAINED];
__device__ float g_sfast[(size_t)S_DIM * DOUT];
__device__ __half g_xh[(size_t)S_DIM * DIN];
__device__ __half g_wh[(size_t)DOUT * DIN];
__device__ unsigned short g_key[(size_t)S_DIM * DOUT];
__device__ int  g_nz_cnt;
__device__ int2 g_nz[LIST_CAP];
__device__ int  g_bd_cnt;
__device__ int2 g_bd[LIST_CAP];

// ---------------------------------------------------------------------------
__global__ void init_kernel() {
    int i = blockIdx.x * blockDim.x + threadIdx.x;
    if (i < DOUT) g_counts[i] = 0;
    if (i == 0) { g_pos = 0; g_nz_cnt = 0; g_bd_cnt = 0; }
}

// ---------------------------------------------------------------------------
// Exact f32 -> f16 pre-conversion (values are f16 images). 8 elems/thread.
// ---------------------------------------------------------------------------
__global__ void convert_kernel(const float* __restrict__ src,
                               __half* __restrict__ dst, int n8) {
    int i = blockIdx.x * blockDim.x + threadIdx.x;
    if (i >= n8) return;
    float4 v0 = *((const float4*)src + i * 2);
    float4 v1 = *((const float4*)src + i * 2 + 1);
    uint4 p;
    ((__half2*)&p)[0] = __floats2half2_rn(v0.x, v0.y);
    ((__half2*)&p)[1] = __floats2half2_rn(v0.z, v0.w);
    ((__half2*)&p)[2] = __floats2half2_rn(v1.x, v1.y);
    ((__half2*)&p)[3] = __floats2half2_rn(v1.z, v1.w);
    *((uint4*)dst + i) = p;
}

// ---------------------------------------------------------------------------
// Flag / key helpers (validated rounds 9-15)
// ---------------------------------------------------------------------------
__device__ __forceinline__ unsigned short hnext(unsigned short b) {
    if (b == 0x8000u) return 0x0001u;
    return (b & 0x8000u) ? (unsigned short)(b - 1) : (unsigned short)(b + 1);
}
__device__ __forceinline__ unsigned short hprev(unsigned short b) {
    if (b == 0x0000u) return 0x8001u;
    return (b & 0x8000u) ? (unsigned short)(b + 1) : (unsigned short)(b - 1);
}
__device__ __forceinline__ bool unsafe_val(float s) {
    __half h = __float2half_rn(s);
    unsigned short b = __half_as_ushort(h);
    float hv = __half2float(h);
    float up = __half2float(__ushort_as_half(hnext(b)));
    float dn = __half2float(__ushort_as_half(hprev(b)));
    return (0.5f * (hv + up) - s < T_FLAG) || (s - 0.5f * (hv + dn) < T_FLAG);
}
__device__ __forceinline__ unsigned key16f(float f) {
    unsigned short b = __half_as_ushort(__float2half(f));
    if (b == 0x8000u) b = 0;
    return (b & 0x8000u) ? (unsigned)(0xFFFFu ^ b) : (unsigned)(b | 0x8000u);
}

// ---------------------------------------------------------------------------
// FAST GEMM: f16 wmma, f32 acc, cp.async 2-stage, 128x128 tile, GBK=64,
// warp tile 64x32 (acc=64 regs) -> ~110 regs/thread -> 2 CTAs/SM (16 warps).
// Per-element chunk order ascending (bit-identical g_sfast).
// ---------------------------------------------------------------------------
#define GBM 128
#define GBN 128
#define GBK 64
#define PAD 72   // halves per smem row (144B: conflict-free ldmatrix)
#define STAGE_HALVES ((GBM + GBN) * PAD)

__device__ __forceinline__ void cp16(void* dst, const void* src) {
    unsigned ds = (unsigned)__cvta_generic_to_shared(dst);
    asm volatile("cp.async.cg.shared.global [%0], [%1], 16;"
                 :: "r"(ds), "l"(src));
}

__global__ void __launch_bounds__(256, 2) gemm_fast_kernel(float* __restrict__ gs) {
    extern __shared__ char smem[];
    __half* stg = (__half*)smem;   // 2 stages: [A 128*PAD | B 128*PAD]

    int tid  = threadIdx.x;
    int warp = tid >> 5;
    int wm   = warp >> 2;          // 0..1 -> 64-row slab
    int wn   = warp & 3;           // 0..3 -> 32-col slab
    int rowBase = blockIdx.y * GBM;
    int colBase = blockIdx.x * GBN;

    wmma::fragment<wmma::accumulator, 16, 16, 16, float> acc[4][2];
#pragma unroll
    for (int i = 0; i < 4; i++)
#pragma unroll
        for (int j = 0; j < 2; j++) wmma::fill_fragment(acc[i][j], 0.0f);

    // loader: A 128 rows x 8 vec8, B 128 rows x 8 vec8 -> 4 cp/thread each
    auto loadStage = [&](int st, int k0) {
        __half* As = stg + st * STAGE_HALVES;
        __half* Bs = As + GBM * PAD;
        const __half* xa = g_xh + (size_t)rowBase * DIN + k0;
        const __half* wb = g_wh + (size_t)colBase * DIN + k0;
#pragma unroll
        for (int p = 0; p < 4; p++) {
            int idx = tid + p * 256;
            int r = idx >> 3, q = idx & 7;
            cp16(&As[r * PAD + q * 8], xa + (size_t)r * DIN + q * 8);
            cp16(&Bs[r * PAD + q * 8], wb + (size_t)r * DIN + q * 8);
        }
        asm volatile("cp.async.commit_group;");
    };

    loadStage(0, 0);

    const int NSTEP = DIN / GBK;   // 64
    for (int c = 0; c < NSTEP; c++) {
        int buf = c & 1;
        asm volatile("cp.async.wait_group 0;");
        __syncthreads();
        if (c + 1 < NSTEP) loadStage((c + 1) & 1, (c + 1) * GBK);
        const __half* Ab = stg + buf * STAGE_HALVES;
        const __half* Bb = Ab + GBM * PAD;
#pragma unroll
        for (int kk = 0; kk < GBK; kk += 16) {
            wmma::fragment<wmma::matrix_a, 16, 16, 16, __half, wmma::row_major> af[4];
            wmma::fragment<wmma::matrix_b, 16, 16, 16, __half, wmma::col_major> bf[2];
#pragma unroll
            for (int i = 0; i < 4; i++)
                wmma::load_matrix_sync(af[i], Ab + (wm * 64 + i * 16) * PAD + kk, PAD);
#pragma unroll
            for (int j = 0; j < 2; j++)
                wmma::load_matrix_sync(bf[j], Bb + (wn * 32 + j * 16) * PAD + kk, PAD);
#pragma unroll
            for (int i = 0; i < 4; i++)
#pragma unroll
                for (int j = 0; j < 2; j++)
                    wmma::mma_sync(acc[i][j], af[i], bf[j], acc[i][j]);
        }
        __syncthreads();
    }

#pragma unroll
    for (int i = 0; i < 4; i++)
#pragma unroll
        for (int j = 0; j < 2; j++) {
            int row = rowBase + wm * 64 + i * 16;
            int col = colBase + wn * 32 + j * 16;
            wmma::store_matrix_sync(gs + (size_t)row * DOUT + col, acc[i][j],
                                    DOUT, wmma::mem_row_major);
        }
}

// ---------------------------------------------------------------------------
// Epilogue: read g_sfast, write tv + u16 key image, count pos, nz list.
// ---------------------------------------------------------------------------
__global__ void epilogue_kernel(const float* __restrict__ bias,
                                float* __restrict__ out) {
    int i = blockIdx.x * blockDim.x + threadIdx.x;   // one float4
    const int total4 = (int)(N_TV / 4);
    int pos = 0;
    if (i < total4) {
        int row = i / (DOUT / 4);
        int c4  = i - row * (DOUT / 4);
        float4 s = *((const float4*)(g_sfast + (size_t)row * DOUT) + c4);
        float4 b = *((const float4*)bias + c4);
        float sv[4] = {s.x, s.y, s.z, s.w};
        float bv[4] = {b.x, b.y, b.z, b.w};
        float tv[4];
        ushort4 kv;
        unsigned short* kp = (unsigned short*)&kv;
#pragma unroll
        for (int e = 0; e < 4; e++) {
            __half hmm = __float2half(sv[e]);
            float tvf = __half2float(hmm) + bv[e];
            __half h = __float2half(tvf);
            tv[e] = __half2float(h);
            kp[e] = (unsigned short)key16f(tv[e]);
            pos += (tv[e] > 0.0f) ? 1 : 0;
            if (fabsf(tv[e]) < NZ_TVMAX) {
                int idx = atomicAdd(&g_nz_cnt, 1);
                if (idx < LIST_CAP) g_nz[idx] = make_int2(row, c4 * 4 + e);
            }
        }
        *((float4*)(out + OFF_TV + (size_t)row * DOUT) + c4) =
            make_float4(tv[0], tv[1], tv[2], tv[3]);
        *((ushort4*)(g_key + (size_t)row * DOUT) + c4) = kv;
    }
#pragma unroll
    for (int off = 16; off; off >>= 1) pos += __shfl_down_sync(~0u, pos, off);
    __shared__ int spos[8];
    if ((threadIdx.x & 31) == 0) spos[threadIdx.x >> 5] = pos;
    __syncthreads();
    if (threadIdx.x == 0) {
        int t = 0;
        for (int k = 0; k < 8; k++) t += spos[k];
        if (t) atomicAdd(&g_pos, t);
    }
}

// ---------------------------------------------------------------------------
// Exact-chain recompute (round-7-bit-identical): ascending k, kc=320 panels.
// ---------------------------------------------------------------------------
__global__ void recompute_list_kernel(const float* __restrict__ bias,
                                      float* __restrict__ out, int which) {
    int cnt = (which == 0) ? g_nz_cnt : g_bd_cnt;
    if (cnt > LIST_CAP) cnt = LIST_CAP;
    const int2* list = (which == 0) ? g_nz : g_bd;
    int posDelta = 0;

    for (int idx = blockIdx.x * blockDim.x + threadIdx.x; idx < cnt;
         idx += gridDim.x * blockDim.x) {
        int row = list[idx].x, col = list[idx].y;
        const __half* xp = g_xh + (size_t)row * DIN;
        const __half* wp = g_wh + (size_t)col * DIN;
        float accT = 0.0f;
        int k = 0;
#pragma unroll 1
        for (int t = 0; t < 13; t++) {
            int kend = (t < 12) ? (t + 1) * 320 : DIN;
            float accC = 0.0f;
#pragma unroll 1
            for (; k < kend; k += 16) {
                uint4 xa = *(const uint4*)(xp + k);
                uint4 wa = *(const uint4*)(wp + k);
                uint4 xb = *(const uint4*)(xp + k + 8);
                uint4 wb = *(const uint4*)(wp + k + 8);
#pragma unroll
                for (int q = 0; q < 4; q++) {
                    float2 xf = __half22float2(((const __half2*)&xa)[q]);
                    float2 wf = __half22float2(((const __half2*)&wa)[q]);
                    accC = __fmaf_rn(xf.x, wf.x, accC);
                    accC = __fmaf_rn(xf.y, wf.y, accC);
                }
#pragma unroll
                for (int q = 0; q < 4; q++) {
                    float2 xf = __half22float2(((const __half2*)&xb)[q]);
                    float2 wf = __half22float2(((const __half2*)&wb)[q]);
                    accC = __fmaf_rn(xf.x, wf.x, accC);
                    accC = __fmaf_rn(xf.y, wf.y, accC);
                }
            }
            accT = accT + accC;
        }
        __half hmm = __float2half(accT);
        float tvf = __half2float(hmm) + bias[col];
        __half h = __float2half(tvf);
        float hv = __half2float(h);
        size_t o = (size_t)row * DOUT + col;
        float old = out[OFF_TV + o];
        if (which == 0)
            posDelta += ((hv > 0.0f) ? 1 : 0) - ((old > 0.0f) ? 1 : 0);
        out[OFF_TV + o] = hv;
        g_key[o] = (unsigned short)key16f(hv);
    }
    if (which == 0) {
#pragma unroll
        for (int off = 16; off; off >>= 1)
            posDelta += __shfl_down_sync(~0u, posDelta, off);
        if ((threadIdx.x & 31) == 0 && posDelta != 0) atomicAdd(&g_pos, posDelta);
    }
}

// ---------------------------------------------------------------------------
__global__ void limit_kernel() {
    g_limit = (int)floorf((0.2f * (float)g_pos) / 2048.0f);
}

// ---------------------------------------------------------------------------
// Phase A: per row (keys only), fast threshold K; collect flagged band elems.
// ---------------------------------------------------------------------------
__global__ void topmask_find_kernel() {
    int row = blockIdx.x;
    int limit = g_limit;
    if (limit <= 0) return;

    __shared__ int hist[256];
    __shared__ int sB, sChi, sK;
    int tid = threadIdx.x;
    const unsigned short* kr = g_key + (size_t)row * DOUT;

    hist[tid] = 0;
    __syncthreads();
    for (int j = tid; j < DOUT; j += 256)
        atomicAdd(&hist[kr[j] >> 8], 1);
    __syncthreads();
    if (tid == 0) {
        int c = 0, b = 255;
        for (; b > 0; b--) {
            if (c + hist[b] >= limit) break;
            c += hist[b];
        }
        sB = b; sChi = c;
    }
    __syncthreads();
    int b = sB, chi = sChi;

    hist[tid] = 0;
    __syncthreads();
    for (int j = tid; j < DOUT; j += 256) {
        unsigned u = kr[j];
        if ((int)(u >> 8) == b) atomicAdd(&hist[u & 255], 1);
    }
    __syncthreads();
    if (tid == 0) {
        int c = chi, lb = 255;
        for (; lb > 0; lb--) {
            if (c + hist[lb] >= limit) break;
            c += hist[lb];
        }
        sK = (b << 8) | lb;
    }
    __syncthreads();
    int K = sK;

    for (int j = tid; j < DOUT; j += 256) {
        int key = (int)kr[j];
        if (key >= K - BAND && key <= K + BAND) {
            float s = g_sfast[(size_t)row * DOUT + j];
            if (unsafe_val(s)) {
                int idx = atomicAdd(&g_bd_cnt, 1);
                if (idx < LIST_CAP) g_bd[idx] = make_int2(row, j);
            }
        }
    }
}

// ---------------------------------------------------------------------------
// Phase B: exact per-row top-limit selection on corrected keys.
// ---------------------------------------------------------------------------
__global__ void topmask_kernel() {
    int row = blockIdx.x;
    int limit = g_limit;
    if (limit <= 0) return;

    __shared__ int hist[256];
    __shared__ int scan[256];
    __shared__ int sB, sChi, sK, sNeed;
    int tid = threadIdx.x;
    const unsigned short* kr = g_key + (size_t)row * DOUT;

    hist[tid] = 0;
    __syncthreads();
    for (int j = tid; j < DOUT; j += 256)
        atomicAdd(&hist[kr[j] >> 8], 1);
    __syncthreads();
    if (tid == 0) {
        int c = 0, b = 255;
        for (; b > 0; b--) {
            if (c + hist[b] >= limit) break;
            c += hist[b];
        }
        sB = b; sChi = c;
    }
    __syncthreads();
    int b = sB, chi = sChi;

    hist[tid] = 0;
    __syncthreads();
    for (int j = tid; j < DOUT; j += 256) {
        unsigned u = kr[j];
        if ((int)(u >> 8) == b) atomicAdd(&hist[u & 255], 1);
    }
    __syncthreads();
    if (tid == 0) {
        int c = chi, lb = 255;
        for (; lb > 0; lb--) {
            if (c + hist[lb] >= limit) break;
            c += hist[lb];
        }
        sK = (b << 8) | lb;
        sNeed = limit - c;
    }
    __syncthreads();
    unsigned K = (unsigned)sK;
    int need = sNeed;

    int j0 = tid * 43;
    int myTies = 0;
    for (int j = j0; j < j0 + 43; j++) {
        unsigned u = kr[j];
        if (u > K) atomicAdd(&g_counts[j], 1);
        else if (u == K) myTies++;
    }
    scan[tid] = myTies;
    __syncthreads();
    for (int off = 1; off < 256; off <<= 1) {
        int t = (tid >= off) ? scan[tid - off] : 0;
        __syncthreads();
        scan[tid] += t;
        __syncthreads();
    }
    int rank = scan[tid] - myTies;
    if (myTies > 0) {
        for (int j = j0; j < j0 + 43; j++) {
            if (kr[j] == K) {
                if (rank < need) atomicAdd(&g_counts[j], 1);
                rank++;
            }
        }
    }
}

// ---------------------------------------------------------------------------
__global__ void sort_kernel(const float* __restrict__ bias, float* __restrict__ out) {
    extern __shared__ unsigned keys[];
    int tid = threadIdx.x;
    for (int i = tid; i < 16384; i += 1024) {
        int cnt = (i < DOUT) ? g_counts[i] : 0;
        keys[i] = ((unsigned)cnt << 14) | (unsigned)(16383 - i);
    }
    __syncthreads();
    for (unsigned k = 2; k <= 16384; k <<= 1) {
        for (unsigned j = k >> 1; j > 0; j >>= 1) {
            for (int i = tid; i < 16384; i += 1024) {
                unsigned ixj = (unsigned)i ^ j;
                if (ixj > (unsigned)i) {
                    unsigned a = keys[i], c = keys[ixj];
                    bool desc = ((i & k) == 0);
                    if (desc ? (a < c) : (a > c)) { keys[i] = c; keys[ixj] = a; }
                }
            }
            __syncthreads();
        }
    }
    for (int i = tid; i < REMAINED; i += 1024) {
        int idx = 16383 - (int)(keys[i] & 16383u);
        g_indices[i] = idx;
        out[OFF_BIAS + i] = bias[idx];
        out[OFF_IDX + i]  = (float)idx;
    }
}

// ---------------------------------------------------------------------------
__global__ void gather_kernel(const float* __restrict__ w, float* __restrict__ out) {
    int i = blockIdx.x * blockDim.x + threadIdx.x;
    const int total8 = REMAINED * (DIN / 8);
    if (i >= total8) return;
    int r = i / (DIN / 8);
    int c8 = i % (DIN / 8);
    int src = g_indices[r];
    const float* s = w + (size_t)src * DIN + (size_t)c8 * 8;
    float* o = out + OFF_W + (size_t)r * DIN + (size_t)c8 * 8;
    float4 v0 = *(const float4*)(s);
    float4 v1 = *(const float4*)(s + 4);
    *(float4*)(o)     = v0;
    *(float4*)(o + 4) = v1;
}

// ---------------------------------------------------------------------------
extern "C" void kernel_launch(void* const* d_in, const int* in_sizes, int n_in,
                              void* d_out, int out_size) {
    const float* x    = (const float*)d_in[0];
    const float* w    = (const float*)d_in[1];
    const float* bias = (const float*)d_in[2];
    float* out = (float*)d_out;

    static __half* xh_p = nullptr;
    static __half* wh_p = nullptr;
    static float* sfast_p = nullptr;
    if (!xh_p) {
        cudaGetSymbolAddress((void**)&xh_p, g_xh);
        cudaGetSymbolAddress((void**)&wh_p, g_wh);
        cudaGetSymbolAddress((void**)&sfast_p, g_sfast);
    }

    const int gemm_smem = 2 * STAGE_HALVES * 2;   // 73728 B
    cudaFuncSetAttribute(gemm_fast_kernel, cudaFuncAttributeMaxDynamicSharedMemorySize, gemm_smem);
    cudaFuncSetAttribute(sort_kernel, cudaFuncAttributeMaxDynamicSharedMemorySize, 65536);

    init_kernel<<<(DOUT + 255) / 256, 256>>>();
    convert_kernel<<<(S_DIM * DIN / 8 + 255) / 256, 256>>>(x, xh_p, S_DIM * DIN / 8);
    convert_kernel<<<(DOUT * DIN / 8 + 255) / 256, 256>>>(w, wh_p, DOUT * DIN / 8);
    gemm_fast_kernel<<<dim3(DOUT / GBN, S_DIM / GBM), 256, gemm_smem>>>(sfast_p);
    epilogue_kernel<<<(int)((N_TV / 4 + 255) / 256), 256>>>(bias, out);
    recompute_list_kernel<<<64, 256>>>(bias, out, 0);
    limit_kernel<<<1, 1>>>();
    topmask_find_kernel<<<S_DIM, 256>>>();
    recompute_list_kernel<<<64, 256>>>(bias, out, 1);
    topmask_kernel<<<S_DIM, 256>>>();
    sort_kernel<<<1, 1024, 65536>>>(bias, out);
    gather_kernel<<<(REMAINED * (DIN / 8) + 255) / 256, 256>>>(w, out);
}